// round 16
// baseline (speedup 1.0000x reference)
#include <cuda_runtime.h>
#include <cuda_bf16.h>
#include <math.h>

#define T_STEPS 2048
#define L 1024
#define CSZ 16                 // cluster size (nonportable, opt-in)
#define CPC (L / CSZ)          // 64 columns per CTA
#define NT 256                 // 8 warps
#define NW 8
#define TX_BYTES 2048u         // bytes landing in each CTA's sa[x] per step

// Packed exp(transfer): g_Epack[k][lane][col] = uint2{ bf16x2(E[i0],E[i0+1]),
// bf16x2(E[i0+2],E[i0+3]) }[col], i0 = 4*lane + 128*k.
__device__ uint2 g_Epack[8][32][L];   // 2 MB

// ---------------------------------------------------------------------------
// helpers
// ---------------------------------------------------------------------------
__device__ __forceinline__ unsigned smem_u32(const void* p) {
    unsigned a;
    asm("{ .reg .u64 t; cvta.to.shared.u64 t, %1; cvt.u32.u64 %0, t; }"
        : "=r"(a) : "l"(p));
    return a;
}
__device__ __forceinline__ unsigned mapa_u32(unsigned laddr, unsigned rank) {
    unsigned ra;
    asm("mapa.shared::cluster.u32 %0, %1, %2;" : "=r"(ra) : "r"(laddr), "r"(rank));
    return ra;
}
__device__ __forceinline__ void st_cluster_f32(unsigned laddr, unsigned rank, float v) {
    unsigned ra = mapa_u32(laddr, rank);
    asm volatile("st.shared::cluster.f32 [%0], %1;" :: "r"(ra), "f"(v) : "memory");
}
// raw async b64 store: remote data addr + remote mbar addr already mapped
__device__ __forceinline__ void st_async_raw64(unsigned ra, unsigned rm,
                                               unsigned long long v) {
    asm volatile("st.async.shared::cluster.mbarrier::complete_tx::bytes.b64 [%0], %1, [%2];"
                 :: "r"(ra), "l"(v), "r"(rm) : "memory");
}
__device__ __forceinline__ void mbar_init(unsigned mbar, unsigned count) {
    asm volatile("mbarrier.init.shared.b64 [%0], %1;" :: "r"(mbar), "r"(count) : "memory");
}
__device__ __forceinline__ void mbar_arm(unsigned mbar, unsigned bytes) {
    asm volatile("mbarrier.arrive.expect_tx.shared.b64 _, [%0], %1;"
                 :: "r"(mbar), "r"(bytes) : "memory");
}
__device__ __forceinline__ void mbar_wait(unsigned mbar, unsigned parity) {
    asm volatile(
        "{\n\t.reg .pred P;\n\t"
        "WAIT_%=:\n\t"
        "mbarrier.try_wait.parity.acquire.cluster.shared::cta.b64 P, [%0], %1;\n\t"
        "@!P bra WAIT_%=;\n\t"
        "}" :: "r"(mbar), "r"(parity) : "memory");
}
#define CLUSTER_SYNC() do { \
    asm volatile("barrier.cluster.arrive.aligned;" ::: "memory"); \
    asm volatile("barrier.cluster.wait.aligned;"   ::: "memory"); } while (0)

__device__ __forceinline__ __nv_bfloat162 u2b(unsigned u) {
    return *reinterpret_cast<__nv_bfloat162*>(&u);
}
__device__ __forceinline__ unsigned b2u(__nv_bfloat162 b) {
    return *reinterpret_cast<unsigned*>(&b);
}

// ---------------------------------------------------------------------------
// Prep: build g_Epack (coalesced)
// ---------------------------------------------------------------------------
__global__ void crf_prep_E(const float* __restrict__ transfer) {
    int k = blockIdx.x >> 5, l = blockIdx.x & 31;
    int col = threadIdx.x;
    int i0 = 4 * l + 128 * k;
    float e0 = __expf(transfer[(i0 + 0) * L + col]);
    float e1 = __expf(transfer[(i0 + 1) * L + col]);
    float e2 = __expf(transfer[(i0 + 2) * L + col]);
    float e3 = __expf(transfer[(i0 + 3) * L + col]);
    g_Epack[k][l][col] = make_uint2(b2u(__floats2bfloat162_rn(e0, e1)),
                                    b2u(__floats2bfloat162_rn(e2, e3)));
}

// ---------------------------------------------------------------------------
// Cluster forward kernel — R14 structure; b64 packed pushes + HMUL2 init.
// ---------------------------------------------------------------------------
__global__ void __launch_bounds__(NT, 1)
crf_cluster_kernel(const float* __restrict__ feats,
                   const float* __restrict__ transfer,
                   const int*   __restrict__ target,
                   float* __restrict__ out) {
    __shared__ __align__(16) __nv_bfloat16 sa[2][L];   // 4 KB double-buffered
    __shared__ __align__(8) unsigned long long smbar[2];
    __shared__ float sgold[CSZ];
    __shared__ float sred[NW];

    const int tid  = threadIdx.x;
    const int w    = tid >> 5;
    const int lane = tid & 31;
    const int bit4 = (lane >> 4) & 1;
    const int bit3 = (lane >> 3) & 1;
    const int q    = 2 * bit4 + bit3;      // this lane's word (2 cols)
    unsigned rank;
    asm("mov.u32 %0, %%cluster_ctarank;" : "=r"(rank));
    const int col0 = rank * CPC;
    const int wcol = col0 + w * 8;         // warp's 8-column base (global)

    const unsigned mb0 = smem_u32(&smbar[0]);
    const unsigned mb1 = smem_u32(&smbar[1]);

    // --- E into registers: E[c][k][p]  (R14 layout, proven) ---
    __nv_bfloat162 E[8][8][2];
    #pragma unroll
    for (int k = 0; k < 8; k++) {
        #pragma unroll
        for (int cp = 0; cp < 4; cp++) {
            uint4 t4 = *(const uint4*)&g_Epack[k][lane][wcol + 2 * cp];
            E[2 * cp + 0][k][0] = u2b(t4.x);  E[2 * cp + 0][k][1] = u2b(t4.y);
            E[2 * cp + 1][k][0] = u2b(t4.z);  E[2 * cp + 1][k][1] = u2b(t4.w);
        }
    }

    // --- mbarriers: init + arm both ---
    if (tid == 0) {
        mbar_init(mb0, 1);
        mbar_init(mb1, 1);
        mbar_arm(mb0, TX_BYTES);
        mbar_arm(mb1, TX_BYTES);
    }

    // --- hoisted remote addresses (loop-invariant) ---
    // b64 packet covers 4 cols at sa[buf][col0 + 8w + 4*bit4] (8B aligned).
    const unsigned r0 = (unsigned)(lane & 7) * 2;
    const unsigned la0 = smem_u32(&sa[0][col0 + 8 * w + 4 * bit4]);
    const unsigned la1 = smem_u32(&sa[1][col0 + 8 * w + 4 * bit4]);
    const unsigned RA0a = mapa_u32(la0, r0),  RA0b = mapa_u32(la0, r0 + 1);
    const unsigned RA1a = mapa_u32(la1, r0),  RA1b = mapa_u32(la1, r0 + 1);
    const unsigned RM0a = mapa_u32(mb0, r0),  RM0b = mapa_u32(mb0, r0 + 1);
    const unsigned RM1a = mapa_u32(mb1, r0),  RM1b = mapa_u32(mb1, r0 + 1);
    const bool pusher = (bit3 == 0);

    // --- bootstrap a_0 = exp(feats[0]) (identical bits in every CTA) ---
    for (int n = tid; n < L; n += NT)
        sa[0][n] = __float2bfloat16(__expf(feats[n]));

    // --- gold partial for t in [rank*128, (rank+1)*128), pushed to rank 0 ---
    {
        float s = 0.f;
        int tbase = rank * (T_STEPS / CSZ);
        for (int t = tbase + tid; t < tbase + T_STEPS / CSZ; t += NT) {
            int lab = target[t];
            s += feats[t * L + lab];
            if (t < T_STEPS - 1) s += transfer[lab * L + target[t + 1]];
        }
        #pragma unroll
        for (int o = 16; o; o >>= 1) s += __shfl_xor_sync(0xffffffffu, s, o);
        if (lane == 0) sred[w] = s;
        __syncthreads();
        if (tid == 0) {
            float g = 0.f;
            #pragma unroll
            for (int qq = 0; qq < NW; qq++) g += sred[qq];
            st_cluster_f32(smem_u32(&sgold[rank]), 0, g);
        }
    }
    CLUSTER_SYNC();   // E regs / a_0 / gold / mbarrier init visible cluster-wide

    int K = 0;
    int p0 = 0, p1 = 0;

    float2 fpre = __ldg((const float2*)&feats[1 * L + wcol + 2 * q]);

#define STEP_BODY(T_, CUR_, NXT_, MBC_, PC_, RAa_, RAb_, RMa_, RMb_, DO_WAIT_)  \
    do {                                                                        \
        float2 fcur_ = fpre;                                                    \
        int tn_ = ((T_) + 2 < T_STEPS) ? ((T_) + 2) : (T_STEPS - 1);            \
        fpre = __ldg((const float2*)&feats[tn_ * L + wcol + 2 * q]);            \
        float ex_ = __expf(fcur_.x);          /* MUFU before the wait */        \
        float ey_ = __expf(fcur_.y);                                            \
        if (DO_WAIT_) {                                                         \
            mbar_wait(MBC_, PC_); PC_ ^= 1;                                     \
            if (tid == 0) mbar_arm(MBC_, TX_BYTES);                             \
        }                                                                       \
        unsigned short us_ = __bfloat16_as_ushort(sa[CUR_][0]);                 \
        int d_ = (int)((us_ >> 7) & 0xFF) - 127;                                \
        K += d_;                                                                \
        float scale_ = __int_as_float((127 - d_) << 23);                        \
        float emx_ = ex_ * scale_, emy_ = ey_ * scale_;                         \
        __nv_bfloat162 acc_[8][2];                                              \
        {   /* k = 0 : HMUL2 init (bit-identical to fma with 0 acc) */          \
            uint2 a2_ = *(const uint2*)&sa[CUR_][4 * lane];                     \
            __nv_bfloat162 aA_ = u2b(a2_.x), aB_ = u2b(a2_.y);                  \
            _Pragma("unroll")                                                   \
            for (int c = 0; c < 8; c++) {                                       \
                acc_[c][0] = __hmul2(aA_, E[c][0][0]);                          \
                acc_[c][1] = __hmul2(aB_, E[c][0][1]);                          \
            }                                                                   \
        }                                                                       \
        _Pragma("unroll")                                                       \
        for (int k = 1; k < 8; k++) {                                           \
            uint2 a2_ = *(const uint2*)&sa[CUR_][4 * lane + 128 * k];           \
            __nv_bfloat162 aA_ = u2b(a2_.x), aB_ = u2b(a2_.y);                  \
            _Pragma("unroll")                                                   \
            for (int c = 0; c < 8; c++) {                                       \
                acc_[c][0] = __hfma2(aA_, E[c][k][0], acc_[c][0]);              \
                acc_[c][1] = __hfma2(aB_, E[c][k][1], acc_[c][1]);              \
            }                                                                   \
        }                                                                       \
        float cs_[8];                                                           \
        _Pragma("unroll")                                                       \
        for (int c = 0; c < 8; c++) {                                           \
            __nv_bfloat162 h_ = __hadd2(acc_[c][0], acc_[c][1]);                \
            cs_[c] = __bfloat162float(__low2bfloat16(h_)) +                     \
                     __bfloat162float(__high2bfloat16(h_));                     \
        }                                                                       \
        float n0_, n1_, n2_, n3_;                                               \
        {                                                                       \
            float s0_ = bit4 ? cs_[0] : cs_[4], k0_ = bit4 ? cs_[4] : cs_[0];   \
            float s1_ = bit4 ? cs_[1] : cs_[5], k1_ = bit4 ? cs_[5] : cs_[1];   \
            float s2_ = bit4 ? cs_[2] : cs_[6], k2_ = bit4 ? cs_[6] : cs_[2];   \
            float s3_ = bit4 ? cs_[3] : cs_[7], k3_ = bit4 ? cs_[7] : cs_[3];   \
            n0_ = k0_ + __shfl_xor_sync(0xffffffffu, s0_, 16);                  \
            n1_ = k1_ + __shfl_xor_sync(0xffffffffu, s1_, 16);                  \
            n2_ = k2_ + __shfl_xor_sync(0xffffffffu, s2_, 16);                  \
            n3_ = k3_ + __shfl_xor_sync(0xffffffffu, s3_, 16);                  \
        }                                                                       \
        float v0_, v1_;                                                         \
        {                                                                       \
            float s0_ = bit3 ? n0_ : n2_, k0_ = bit3 ? n2_ : n0_;               \
            float s1_ = bit3 ? n1_ : n3_, k1_ = bit3 ? n3_ : n1_;               \
            v0_ = k0_ + __shfl_xor_sync(0xffffffffu, s0_, 8);                   \
            v1_ = k1_ + __shfl_xor_sync(0xffffffffu, s1_, 8);                   \
        }                                                                       \
        _Pragma("unroll")                                                       \
        for (int o = 4; o; o >>= 1) {                                           \
            v0_ += __shfl_xor_sync(0xffffffffu, v0_, o);                        \
            v1_ += __shfl_xor_sync(0xffffffffu, v1_, o);                        \
        }                                                                       \
        unsigned val_ = b2u(__floats2bfloat162_rn(v0_ * emx_, v1_ * emy_));     \
        /* partner word (q^1): swap bit3; partner packed its own emission */    \
        unsigned oth_ = __shfl_xor_sync(0xffffffffu, val_, 8);                  \
        if (pusher) {                                                           \
            unsigned long long pkt_ =                                           \
                ((unsigned long long)oth_ << 32) | (unsigned long long)val_;    \
            st_async_raw64(RAa_, RMa_, pkt_);                                   \
            st_async_raw64(RAb_, RMb_, pkt_);                                   \
        }                                                                       \
    } while (0)

    // peeled t = 0 : buf0 -> buf1, no wait (local bootstrap)
    STEP_BODY(0, 0, 1, mb0, p0, RA1a, RA1b, RM1a, RM1b, 0);

    // pairs t = 1..2046 (1023 iterations)
    for (int t = 1; t < T_STEPS - 1; t += 2) {
        STEP_BODY(t,     1, 0, mb1, p1, RA0a, RA0b, RM0a, RM0b, 1);
        STEP_BODY(t + 1, 0, 1, mb0, p0, RA1a, RA1b, RM1a, RM1b, 1);
    }
#undef STEP_BODY

    // final buffer (a_{T-1} lives in buf1) fully delivered before exit
    mbar_wait(mb1, p1);

    // --- epilogue: rank 0 computes the loss ---
    if (rank == 0) {
        uint2 a2 = *(const uint2*)&sa[1][4 * tid];
        __nv_bfloat162 x0 = u2b(a2.x), x1 = u2b(a2.y);
        float s = __bfloat162float(__low2bfloat16(x0)) +
                  __bfloat162float(__high2bfloat16(x0)) +
                  __bfloat162float(__low2bfloat16(x1)) +
                  __bfloat162float(__high2bfloat16(x1));
        #pragma unroll
        for (int o = 16; o; o >>= 1) s += __shfl_xor_sync(0xffffffffu, s, o);
        if (lane == 0) sred[w] = s;
        __syncthreads();
        if (tid == 0) {
            float tot = 0.f;
            #pragma unroll
            for (int qq = 0; qq < NW; qq++) tot += sred[qq];
            float gold = 0.f;
            #pragma unroll
            for (int r = 0; r < CSZ; r++) gold += sgold[r];
            double lz = log((double)tot) + (double)K * 0.69314718055994530942;
            out[0] = (float)(lz - (double)gold);
        }
    }
}

extern "C" void kernel_launch(void* const* d_in, const int* in_sizes, int n_in,
                              void* d_out, int out_size) {
    const float* feats    = (const float*)d_in[0];   // [2048, 1024] f32
    const float* transfer = (const float*)d_in[1];   // [1024, 1024] f32
    const int*   target   = (const int*)d_in[2];     // [2048] i32
    float* out = (float*)d_out;

    cudaFuncSetAttribute(crf_cluster_kernel,
                         cudaFuncAttributeNonPortableClusterSizeAllowed, 1);

    crf_prep_E<<<256, 1024>>>(transfer);

    cudaLaunchConfig_t cfg = {};
    cfg.gridDim  = dim3(CSZ, 1, 1);
    cfg.blockDim = dim3(NT, 1, 1);
    cfg.dynamicSmemBytes = 0;
    cfg.stream = 0;
    cudaLaunchAttribute attrs[1];
    attrs[0].id = cudaLaunchAttributeClusterDimension;
    attrs[0].val.clusterDim.x = CSZ;
    attrs[0].val.clusterDim.y = 1;
    attrs[0].val.clusterDim.z = 1;
    cfg.attrs = attrs;
    cfg.numAttrs = 1;

    cudaLaunchKernelEx(&cfg, crf_cluster_kernel, feats, transfer, target, out);
}

// round 17
// speedup vs baseline: 1.0461x; 1.0461x over previous
#include <cuda_runtime.h>
#include <cuda_bf16.h>
#include <math.h>

#define T_STEPS 2048
#define L 1024
#define CSZ 16                 // cluster size (nonportable, opt-in)
#define CPC (L / CSZ)          // 64 columns per CTA
#define NT 256                 // 8 warps
#define NW 8
#define TX_BYTES 2048u         // bytes landing in each CTA's sa[x] per step

// Packed exp(transfer): g_Epack[k][lane][col] = uint2{ bf16x2(E[i0],E[i0+1]),
// bf16x2(E[i0+2],E[i0+3]) }[col], i0 = 4*lane + 128*k.
__device__ uint2 g_Epack[8][32][L];   // 2 MB

// ---------------------------------------------------------------------------
// helpers
// ---------------------------------------------------------------------------
__device__ __forceinline__ unsigned smem_u32(const void* p) {
    unsigned a;
    asm("{ .reg .u64 t; cvta.to.shared.u64 t, %1; cvt.u32.u64 %0, t; }"
        : "=r"(a) : "l"(p));
    return a;
}
__device__ __forceinline__ unsigned mapa_u32(unsigned laddr, unsigned rank) {
    unsigned ra;
    asm("mapa.shared::cluster.u32 %0, %1, %2;" : "=r"(ra) : "r"(laddr), "r"(rank));
    return ra;
}
__device__ __forceinline__ void st_cluster_f32(unsigned laddr, unsigned rank, float v) {
    unsigned ra = mapa_u32(laddr, rank);
    asm volatile("st.shared::cluster.f32 [%0], %1;" :: "r"(ra), "f"(v) : "memory");
}
// raw async store: remote data addr + remote mbar addr already mapped
__device__ __forceinline__ void st_async_raw(unsigned ra, unsigned rm, unsigned v) {
    asm volatile("st.async.shared::cluster.mbarrier::complete_tx::bytes.b32 [%0], %1, [%2];"
                 :: "r"(ra), "r"(v), "r"(rm) : "memory");
}
__device__ __forceinline__ void mbar_init(unsigned mbar, unsigned count) {
    asm volatile("mbarrier.init.shared.b64 [%0], %1;" :: "r"(mbar), "r"(count) : "memory");
}
__device__ __forceinline__ void mbar_arm(unsigned mbar, unsigned bytes) {
    asm volatile("mbarrier.arrive.expect_tx.shared.b64 _, [%0], %1;"
                 :: "r"(mbar), "r"(bytes) : "memory");
}
__device__ __forceinline__ void mbar_wait(unsigned mbar, unsigned parity) {
    asm volatile(
        "{\n\t.reg .pred P;\n\t"
        "WAIT_%=:\n\t"
        "mbarrier.try_wait.parity.acquire.cluster.shared::cta.b64 P, [%0], %1;\n\t"
        "@!P bra WAIT_%=;\n\t"
        "}" :: "r"(mbar), "r"(parity) : "memory");
}
#define CLUSTER_SYNC() do { \
    asm volatile("barrier.cluster.arrive.aligned;" ::: "memory"); \
    asm volatile("barrier.cluster.wait.aligned;"   ::: "memory"); } while (0)

__device__ __forceinline__ __nv_bfloat162 u2b(unsigned u) {
    return *reinterpret_cast<__nv_bfloat162*>(&u);
}
__device__ __forceinline__ unsigned b2u(__nv_bfloat162 b) {
    return *reinterpret_cast<unsigned*>(&b);
}

// ---------------------------------------------------------------------------
// Prep: build g_Epack (coalesced)
// ---------------------------------------------------------------------------
__global__ void crf_prep_E(const float* __restrict__ transfer) {
    int k = blockIdx.x >> 5, l = blockIdx.x & 31;
    int col = threadIdx.x;
    int i0 = 4 * l + 128 * k;
    float e0 = __expf(transfer[(i0 + 0) * L + col]);
    float e1 = __expf(transfer[(i0 + 1) * L + col]);
    float e2 = __expf(transfer[(i0 + 2) * L + col]);
    float e3 = __expf(transfer[(i0 + 3) * L + col]);
    g_Epack[k][l][col] = make_uint2(b2u(__floats2bfloat162_rn(e0, e1)),
                                    b2u(__floats2bfloat162_rn(e2, e3)));
}

// ---------------------------------------------------------------------------
// Cluster forward kernel — R14 structure exactly; only change: HMUL2 init
// of the k=0 matvec iteration (bit-identical, removes 16 zero-MOVs/lane).
// ---------------------------------------------------------------------------
__global__ void __launch_bounds__(NT, 1)
crf_cluster_kernel(const float* __restrict__ feats,
                   const float* __restrict__ transfer,
                   const int*   __restrict__ target,
                   float* __restrict__ out) {
    __shared__ __align__(16) __nv_bfloat16 sa[2][L];   // 4 KB double-buffered
    __shared__ __align__(8) unsigned long long smbar[2];
    __shared__ float sgold[CSZ];
    __shared__ float sred[NW];

    const int tid  = threadIdx.x;
    const int w    = tid >> 5;
    const int lane = tid & 31;
    const int bit4 = (lane >> 4) & 1;
    const int bit3 = (lane >> 3) & 1;
    const int q    = 2 * bit4 + bit3;      // this lane's word (2 cols)
    unsigned rank;
    asm("mov.u32 %0, %%cluster_ctarank;" : "=r"(rank));
    const int col0 = rank * CPC;
    const int wcol = col0 + w * 8;         // warp's 8-column base (global)

    const unsigned mb0 = smem_u32(&smbar[0]);
    const unsigned mb1 = smem_u32(&smbar[1]);

    // --- E into registers: E[c][k][p]  (R14 layout, proven) ---
    __nv_bfloat162 E[8][8][2];
    #pragma unroll
    for (int k = 0; k < 8; k++) {
        #pragma unroll
        for (int cp = 0; cp < 4; cp++) {
            uint4 t4 = *(const uint4*)&g_Epack[k][lane][wcol + 2 * cp];
            E[2 * cp + 0][k][0] = u2b(t4.x);  E[2 * cp + 0][k][1] = u2b(t4.y);
            E[2 * cp + 1][k][0] = u2b(t4.z);  E[2 * cp + 1][k][1] = u2b(t4.w);
        }
    }

    // --- mbarriers: init + arm both ---
    if (tid == 0) {
        mbar_init(mb0, 1);
        mbar_init(mb1, 1);
        mbar_arm(mb0, TX_BYTES);
        mbar_arm(mb1, TX_BYTES);
    }

    // --- hoisted remote addresses (loop-invariant) ---
    const unsigned r0 = (unsigned)(lane & 7) * 2;
    const unsigned la0 = smem_u32(&sa[0][col0 + 8 * w + 2 * q]);
    const unsigned la1 = smem_u32(&sa[1][col0 + 8 * w + 2 * q]);
    const unsigned RA0a = mapa_u32(la0, r0),  RA0b = mapa_u32(la0, r0 + 1);
    const unsigned RA1a = mapa_u32(la1, r0),  RA1b = mapa_u32(la1, r0 + 1);
    const unsigned RM0a = mapa_u32(mb0, r0),  RM0b = mapa_u32(mb0, r0 + 1);
    const unsigned RM1a = mapa_u32(mb1, r0),  RM1b = mapa_u32(mb1, r0 + 1);

    // --- bootstrap a_0 = exp(feats[0]) (identical bits in every CTA) ---
    for (int n = tid; n < L; n += NT)
        sa[0][n] = __float2bfloat16(__expf(feats[n]));

    // --- gold partial for t in [rank*128, (rank+1)*128), pushed to rank 0 ---
    {
        float s = 0.f;
        int tbase = rank * (T_STEPS / CSZ);
        for (int t = tbase + tid; t < tbase + T_STEPS / CSZ; t += NT) {
            int lab = target[t];
            s += feats[t * L + lab];
            if (t < T_STEPS - 1) s += transfer[lab * L + target[t + 1]];
        }
        #pragma unroll
        for (int o = 16; o; o >>= 1) s += __shfl_xor_sync(0xffffffffu, s, o);
        if (lane == 0) sred[w] = s;
        __syncthreads();
        if (tid == 0) {
            float g = 0.f;
            #pragma unroll
            for (int qq = 0; qq < NW; qq++) g += sred[qq];
            st_cluster_f32(smem_u32(&sgold[rank]), 0, g);
        }
    }
    CLUSTER_SYNC();   // E regs / a_0 / gold / mbarrier init visible cluster-wide

    int K = 0;
    int p0 = 0, p1 = 0;

    float2 fpre = __ldg((const float2*)&feats[1 * L + wcol + 2 * q]);

#define STEP_BODY(T_, CUR_, NXT_, MBC_, PC_, RAa_, RAb_, RMa_, RMb_, DO_WAIT_)  \
    do {                                                                        \
        float2 fcur_ = fpre;                                                    \
        int tn_ = ((T_) + 2 < T_STEPS) ? ((T_) + 2) : (T_STEPS - 1);            \
        fpre = __ldg((const float2*)&feats[tn_ * L + wcol + 2 * q]);            \
        float ex_ = __expf(fcur_.x);          /* MUFU before the wait */        \
        float ey_ = __expf(fcur_.y);                                            \
        if (DO_WAIT_) {                                                         \
            mbar_wait(MBC_, PC_); PC_ ^= 1;                                     \
            if (tid == 0) mbar_arm(MBC_, TX_BYTES);                             \
        }                                                                       \
        unsigned short us_ = __bfloat16_as_ushort(sa[CUR_][0]);                 \
        int d_ = (int)((us_ >> 7) & 0xFF) - 127;                                \
        K += d_;                                                                \
        float scale_ = __int_as_float((127 - d_) << 23);                        \
        float emx_ = ex_ * scale_, emy_ = ey_ * scale_;                         \
        __nv_bfloat162 acc_[8][2];                                              \
        {   /* k = 0 : HMUL2 init (bit-identical to fma with zero acc) */       \
            uint2 a2_ = *(const uint2*)&sa[CUR_][4 * lane];                     \
            __nv_bfloat162 aA_ = u2b(a2_.x), aB_ = u2b(a2_.y);                  \
            _Pragma("unroll")                                                   \
            for (int c = 0; c < 8; c++) {                                       \
                acc_[c][0] = __hmul2(aA_, E[c][0][0]);                          \
                acc_[c][1] = __hmul2(aB_, E[c][0][1]);                          \
            }                                                                   \
        }                                                                       \
        _Pragma("unroll")                                                       \
        for (int k = 1; k < 8; k++) {                                           \
            uint2 a2_ = *(const uint2*)&sa[CUR_][4 * lane + 128 * k];           \
            __nv_bfloat162 aA_ = u2b(a2_.x), aB_ = u2b(a2_.y);                  \
            _Pragma("unroll")                                                   \
            for (int c = 0; c < 8; c++) {                                       \
                acc_[c][0] = __hfma2(aA_, E[c][k][0], acc_[c][0]);              \
                acc_[c][1] = __hfma2(aB_, E[c][k][1], acc_[c][1]);              \
            }                                                                   \
        }                                                                       \
        float cs_[8];                                                           \
        _Pragma("unroll")                                                       \
        for (int c = 0; c < 8; c++) {                                           \
            __nv_bfloat162 h_ = __hadd2(acc_[c][0], acc_[c][1]);                \
            cs_[c] = __bfloat162float(__low2bfloat16(h_)) +                     \
                     __bfloat162float(__high2bfloat16(h_));                     \
        }                                                                       \
        float n0_, n1_, n2_, n3_;                                               \
        {                                                                       \
            float s0_ = bit4 ? cs_[0] : cs_[4], k0_ = bit4 ? cs_[4] : cs_[0];   \
            float s1_ = bit4 ? cs_[1] : cs_[5], k1_ = bit4 ? cs_[5] : cs_[1];   \
            float s2_ = bit4 ? cs_[2] : cs_[6], k2_ = bit4 ? cs_[6] : cs_[2];   \
            float s3_ = bit4 ? cs_[3] : cs_[7], k3_ = bit4 ? cs_[7] : cs_[3];   \
            n0_ = k0_ + __shfl_xor_sync(0xffffffffu, s0_, 16);                  \
            n1_ = k1_ + __shfl_xor_sync(0xffffffffu, s1_, 16);                  \
            n2_ = k2_ + __shfl_xor_sync(0xffffffffu, s2_, 16);                  \
            n3_ = k3_ + __shfl_xor_sync(0xffffffffu, s3_, 16);                  \
        }                                                                       \
        float v0_, v1_;                                                         \
        {                                                                       \
            float s0_ = bit3 ? n0_ : n2_, k0_ = bit3 ? n2_ : n0_;               \
            float s1_ = bit3 ? n1_ : n3_, k1_ = bit3 ? n3_ : n1_;               \
            v0_ = k0_ + __shfl_xor_sync(0xffffffffu, s0_, 8);                   \
            v1_ = k1_ + __shfl_xor_sync(0xffffffffu, s1_, 8);                   \
        }                                                                       \
        _Pragma("unroll")                                                       \
        for (int o = 4; o; o >>= 1) {                                           \
            v0_ += __shfl_xor_sync(0xffffffffu, v0_, o);                        \
            v1_ += __shfl_xor_sync(0xffffffffu, v1_, o);                        \
        }                                                                       \
        unsigned val_ = b2u(__floats2bfloat162_rn(v0_ * emx_, v1_ * emy_));     \
        st_async_raw(RAa_, RMa_, val_);                                         \
        st_async_raw(RAb_, RMb_, val_);                                         \
    } while (0)

    // peeled t = 0 : buf0 -> buf1, no wait (local bootstrap)
    STEP_BODY(0, 0, 1, mb0, p0, RA1a, RA1b, RM1a, RM1b, 0);

    // pairs t = 1..2046 (1023 iterations)
    for (int t = 1; t < T_STEPS - 1; t += 2) {
        STEP_BODY(t,     1, 0, mb1, p1, RA0a, RA0b, RM0a, RM0b, 1);
        STEP_BODY(t + 1, 0, 1, mb0, p0, RA1a, RA1b, RM1a, RM1b, 1);
    }
#undef STEP_BODY

    // final buffer (a_{T-1} lives in buf1) fully delivered before exit
    mbar_wait(mb1, p1);

    // --- epilogue: rank 0 computes the loss ---
    if (rank == 0) {
        uint2 a2 = *(const uint2*)&sa[1][4 * tid];
        __nv_bfloat162 x0 = u2b(a2.x), x1 = u2b(a2.y);
        float s = __bfloat162float(__low2bfloat16(x0)) +
                  __bfloat162float(__high2bfloat16(x0)) +
                  __bfloat162float(__low2bfloat16(x1)) +
                  __bfloat162float(__high2bfloat16(x1));
        #pragma unroll
        for (int o = 16; o; o >>= 1) s += __shfl_xor_sync(0xffffffffu, s, o);
        if (lane == 0) sred[w] = s;
        __syncthreads();
        if (tid == 0) {
            float tot = 0.f;
            #pragma unroll
            for (int qq = 0; qq < NW; qq++) tot += sred[qq];
            float gold = 0.f;
            #pragma unroll
            for (int r = 0; r < CSZ; r++) gold += sgold[r];
            double lz = log((double)tot) + (double)K * 0.69314718055994530942;
            out[0] = (float)(lz - (double)gold);
        }
    }
}

extern "C" void kernel_launch(void* const* d_in, const int* in_sizes, int n_in,
                              void* d_out, int out_size) {
    const float* feats    = (const float*)d_in[0];   // [2048, 1024] f32
    const float* transfer = (const float*)d_in[1];   // [1024, 1024] f32
    const int*   target   = (const int*)d_in[2];     // [2048] i32
    float* out = (float*)d_out;

    cudaFuncSetAttribute(crf_cluster_kernel,
                         cudaFuncAttributeNonPortableClusterSizeAllowed, 1);

    crf_prep_E<<<256, 1024>>>(transfer);

    cudaLaunchConfig_t cfg = {};
    cfg.gridDim  = dim3(CSZ, 1, 1);
    cfg.blockDim = dim3(NT, 1, 1);
    cfg.dynamicSmemBytes = 0;
    cfg.stream = 0;
    cudaLaunchAttribute attrs[1];
    attrs[0].id = cudaLaunchAttributeClusterDimension;
    attrs[0].val.clusterDim.x = CSZ;
    attrs[0].val.clusterDim.y = 1;
    attrs[0].val.clusterDim.z = 1;
    cfg.attrs = attrs;
    cfg.numAttrs = 1;

    cudaLaunchKernelEx(&cfg, crf_cluster_kernel, feats, transfer, target, out);
}